// round 2
// baseline (speedup 1.0000x reference)
#include <cuda_runtime.h>
#include <cstdint>

// Problem shape (fixed by the dataset)
static constexpr int B  = 64;
static constexpr int NN = 20000;
static constexpr int E  = 1280000;

// Scratch (__device__ globals: no allocation allowed in kernel_launch)
__device__ float4 g_xT[NN * 16];          // x transposed: [N][64]
__device__ int    g_hist[NN];             // per-dst degree
__device__ int    g_off[NN + 1];          // CSR offsets (exclusive scan)
__device__ int    g_cursor[NN];           // running cursors for bin scatter
__device__ float2 g_edge[E];              // sorted edges: {coef, src-as-float-bits}

// ---------------------------------------------------------------------------
// Kernel 1: zero histogram
// ---------------------------------------------------------------------------
__global__ void zero_hist_kernel() {
    int i = blockIdx.x * blockDim.x + threadIdx.x;
    if (i < NN) g_hist[i] = 0;
}

// ---------------------------------------------------------------------------
// Kernel 2: transpose x [B, N] -> xT [N, B]
// ---------------------------------------------------------------------------
__global__ void transpose_kernel(const float* __restrict__ x) {
    __shared__ float tile[32][33];
    float* xT = reinterpret_cast<float*>(g_xT);

    int n0 = blockIdx.x * 32;
    int b0 = blockIdx.y * 32;
    int tx = threadIdx.x;   // 0..31
    int ty = threadIdx.y;   // 0..7

#pragma unroll
    for (int i = 0; i < 32; i += 8)
        tile[ty + i][tx] = x[(b0 + ty + i) * NN + (n0 + tx)];
    __syncthreads();
#pragma unroll
    for (int i = 0; i < 32; i += 8)
        xT[(n0 + ty + i) * B + (b0 + tx)] = tile[tx][ty + i];
}

// ---------------------------------------------------------------------------
// Kernel 3: histogram of dst (vectorized int4 loads, no-return atomics)
// ---------------------------------------------------------------------------
__global__ __launch_bounds__(256) void hist_kernel(const int* __restrict__ dst) {
    int t = blockIdx.x * 256 + threadIdx.x;   // one thread per 4 edges
    if (t * 4 >= E) return;
    int4 d = reinterpret_cast<const int4*>(dst)[t];
    atomicAdd(&g_hist[d.x], 1);
    atomicAdd(&g_hist[d.y], 1);
    atomicAdd(&g_hist[d.z], 1);
    atomicAdd(&g_hist[d.w], 1);
}

// ---------------------------------------------------------------------------
// Kernel 4: exclusive scan over 20000 bins (single CTA of 1024 threads,
// 20 bins per thread + Hillis-Steele block scan)
// ---------------------------------------------------------------------------
__global__ __launch_bounds__(1024) void scan_kernel() {
    __shared__ int sbuf[2][1024];
    int t = threadIdx.x;

    int local[20];
    int run = 0;
#pragma unroll
    for (int i = 0; i < 20; i++) {
        int idx = t * 20 + i;
        int v = (idx < NN) ? g_hist[idx] : 0;
        local[i] = run;
        run += v;
    }
    sbuf[0][t] = run;
    __syncthreads();

    int cur = 0;
    for (int off = 1; off < 1024; off <<= 1) {
        int v = sbuf[cur][t];
        if (t >= off) v += sbuf[cur][t - off];
        sbuf[cur ^ 1][t] = v;
        cur ^= 1;
        __syncthreads();
    }
    int excl = sbuf[cur][t] - run;   // exclusive prefix for this thread's chunk

#pragma unroll
    for (int i = 0; i < 20; i++) {
        int idx = t * 20 + i;
        if (idx < NN) {
            int o = excl + local[i];
            g_off[idx]    = o;
            g_cursor[idx] = o;
        }
    }
    if (t == 1023) g_off[NN] = E;
}

// ---------------------------------------------------------------------------
// Kernel 5: scatter edges into dst-sorted list, packing {coef, src}
// ---------------------------------------------------------------------------
__global__ __launch_bounds__(256) void binscat_kernel(
    const float* __restrict__ adj, const float* __restrict__ w,
    const int* __restrict__ src, const int* __restrict__ dst)
{
    int e = blockIdx.x * 256 + threadIdx.x;
    if (e >= E) return;
    int   d = __ldg(dst + e);
    float c = __ldg(adj + e) * __ldg(w + e);
    int   s = __ldg(src + e);
    int pos = atomicAdd(&g_cursor[d], 1);
    g_edge[pos] = make_float2(c, __int_as_float(s));
}

// ---------------------------------------------------------------------------
// Kernel 6: reduce + fused epilogue.
// One warp per dst node (32 dsts per 1024-thread CTA). Each lane accumulates
// 2 of the 64 batch lanes in registers; no atomics. Then transpose through
// SMEM and write out[b, d0:d0+32] coalesced with self-loop/bias/ReLU fused.
// ---------------------------------------------------------------------------
__global__ __launch_bounds__(1024) void reduce_kernel(
    const float* __restrict__ x,       // row 0 used for self loop
    const float* __restrict__ self_w,
    const float* __restrict__ bias,
    float* __restrict__ out)
{
    __shared__ float tile[32][66];   // [dst-in-block][batch], padded
    __shared__ float s_sl[32], s_b[32];

    int warp = threadIdx.x >> 5;
    int lane = threadIdx.x & 31;
    int d0   = blockIdx.x * 32;
    int d    = d0 + warp;            // 625*32 == 20000 exactly

    if (threadIdx.x < 32) {
        int n = d0 + threadIdx.x;
        s_sl[threadIdx.x] = __ldg(x + n) * __ldg(self_w + n);
        s_b[threadIdx.x]  = __ldg(bias + n);
    }

    int beg = g_off[d];
    int end = g_off[d + 1];
    const float2* xt2 = reinterpret_cast<const float2*>(g_xT);

    float2 a0 = make_float2(0.f, 0.f);
    float2 a1 = make_float2(0.f, 0.f);
    int e = beg;
    for (; e + 1 < end; e += 2) {
        float2 m0 = g_edge[e];
        float2 m1 = g_edge[e + 1];
        float2 v0 = xt2[__float_as_int(m0.y) * 32 + lane];
        float2 v1 = xt2[__float_as_int(m1.y) * 32 + lane];
        a0.x = fmaf(m0.x, v0.x, a0.x);
        a0.y = fmaf(m0.x, v0.y, a0.y);
        a1.x = fmaf(m1.x, v1.x, a1.x);
        a1.y = fmaf(m1.x, v1.y, a1.y);
    }
    if (e < end) {
        float2 m0 = g_edge[e];
        float2 v0 = xt2[__float_as_int(m0.y) * 32 + lane];
        a0.x = fmaf(m0.x, v0.x, a0.x);
        a0.y = fmaf(m0.x, v0.y, a0.y);
    }
    a0.x += a1.x;
    a0.y += a1.y;

    // tile[warp][2*lane .. 2*lane+1] = accumulated row
    *reinterpret_cast<float2*>(&tile[warp][2 * lane]) = a0;
    __syncthreads();

    // Coalesced fused epilogue: thread -> (j = dst-in-block, b = batch)
    int j  = threadIdx.x & 31;
    int b0 = threadIdx.x >> 5;
    float sl = s_sl[j];
    float bb = s_b[j];
#pragma unroll
    for (int k = 0; k < 2; k++) {
        int b = b0 + 32 * k;
        float v = fmaf(tile[j][b], sl, bb);
        out[b * NN + d0 + j] = fmaxf(v, 0.f);
    }
}

// ---------------------------------------------------------------------------
// Launch
// ---------------------------------------------------------------------------
extern "C" void kernel_launch(void* const* d_in, const int* in_sizes, int n_in,
                              void* d_out, int out_size)
{
    const float* x      = (const float*)d_in[0];
    const float* adj    = (const float*)d_in[1];
    const float* w      = (const float*)d_in[2];
    const float* self_w = (const float*)d_in[3];
    const float* bias   = (const float*)d_in[4];
    const int*   src    = (const int*)d_in[5];
    const int*   dst    = (const int*)d_in[6];
    float*       out    = (float*)d_out;

    zero_hist_kernel<<<(NN + 255) / 256, 256>>>();
    transpose_kernel<<<dim3(NN / 32, B / 32), dim3(32, 8)>>>(x);
    hist_kernel<<<(E / 4 + 255) / 256, 256>>>(dst);
    scan_kernel<<<1, 1024>>>();
    binscat_kernel<<<(E + 255) / 256, 256>>>(adj, w, src, dst);
    reduce_kernel<<<NN / 32, 1024>>>(x, self_w, bias, out);
}